// round 14
// baseline (speedup 1.0000x reference)
#include <cuda_runtime.h>
#include <cuda_fp16.h>
#include <cstdint>

// Problem constants: N=4096, D=128, S=32768, NUM_CLASS=500000.
#define DIM 128
#define MAX_S 32768
#define MAX_N 4096
#define NUM_CLASS_MAX 500000

// Scratch: fp16 operands + gathered fp32 bias.
static __device__ __half g_w[(size_t)MAX_S * DIM];
static __device__ __half g_x[(size_t)MAX_N * DIM];
static __device__ float g_bias[MAX_S];
static __device__ int g_ids_is64;

// ---------------------------------------------------------------------------
// Kernel 0a: reset dtype flag. Kernel 0b: parallel detect (benign-race store).
// ---------------------------------------------------------------------------
__global__ void init_flag_kernel() { g_ids_is64 = 1; }

__global__ void detect_ids_kernel(const void* __restrict__ ids, int S) {
    const long long* p = (const long long*)ids;
    int n64 = S / 2;
    int i = blockIdx.x * blockDim.x + threadIdx.x;
    int stride = gridDim.x * blockDim.x;
    int bad = 0;
    for (; i < n64; i += stride) {
        long long v = p[i];
        if (v < 0 || v >= NUM_CLASS_MAX) bad = 1;
    }
    if (__syncthreads_or(bad) && threadIdx.x == 0) g_ids_is64 = 0;
}

__device__ __forceinline__ long long read_id(const void* ids, int s) {
    long long id = g_ids_is64 ? ((const long long*)ids)[s]
                              : (long long)((const int*)ids)[s];
    if (id < 0 || id >= NUM_CLASS_MAX) id = 0;
    return id;
}

// ---------------------------------------------------------------------------
// Kernel 1 (fused): gather weight[ids]->g_w fp16 + bias; convert x->g_x fp16;
// ids pass-through into the output tail (runs BEFORE the GEMM).
// ---------------------------------------------------------------------------
__global__ void prep_kernel(const float* __restrict__ x,
                            const float* __restrict__ w,
                            const float* __restrict__ bias,
                            const void* __restrict__ ids,
                            void* out, long long base, long long extra,
                            int N, int S) {
    int warp = (blockIdx.x * blockDim.x + threadIdx.x) >> 5;
    int lane = threadIdx.x & 31;
    int nwarps = (gridDim.x * blockDim.x) >> 5;
    int total = S + N;
    for (int s = warp; s < total; s += nwarps) {
        const float4* src;
        __half2* dst;
        if (s < S) {
            long long id = read_id(ids, s);
            src = (const float4*)(w + (size_t)id * DIM);
            dst = (__half2*)(g_w + (size_t)s * DIM);
            if (lane == 0) g_bias[s] = bias[id];
        } else {
            int r = s - S;
            src = (const float4*)(x + (size_t)r * DIM);
            dst = (__half2*)(g_x + (size_t)r * DIM);
        }
        float4 v = src[lane];
        dst[lane * 2 + 0] = __float22half2_rn(make_float2(v.x, v.y));
        dst[lane * 2 + 1] = __float22half2_rn(make_float2(v.z, v.w));
    }
    if (extra > 0) {
        int gidx = blockIdx.x * blockDim.x + threadIdx.x;
        int gstride = gridDim.x * blockDim.x;
        for (int s = gidx; s < S; s += gstride) {
            long long id = read_id(ids, s);
            if (extra >= 2LL * S) {
                ((long long*)((float*)out + base))[s] = id;
            } else if (extra >= (long long)S) {
                ((float*)out)[base + s] = (float)id;
            }
        }
    }
}

// ---------------------------------------------------------------------------
// Kernel 2: fp16 GEMM, mma.m16n8k16 + ldmatrix, 256 threads (8 warps, 2x4),
// warp tile 64x32, 2 CTAs/SM. A tile resident across NJ=4 N-tiles; single B
// buffer (B(j+1) prefetch hides under epilogue j + co-resident CTA).
// Epilogue: warp-private smem staging (slot-scrambled, conflict-free) ->
// fully coalesced st.global.cs.v4 (128B wavefronts).
// ---------------------------------------------------------------------------
#define TM 128
#define TN 128
#define NJ 4
#define A_BYTES (TM * DIM * 2)                 // 32768
#define B_BYTES (TN * DIM * 2)                 // 32768
#define STG_BYTES 32768                        // 8 warps x 4KB slabs
#define SM_TOTAL (A_BYTES + B_BYTES + STG_BYTES) // 98304

__device__ __forceinline__ void mma_f16(float c[4], const uint32_t a[4],
                                        const uint32_t b[2]) {
    asm volatile(
        "mma.sync.aligned.m16n8k16.row.col.f32.f16.f16.f32 "
        "{%0,%1,%2,%3}, {%4,%5,%6,%7}, {%8,%9}, {%0,%1,%2,%3};\n"
        : "+f"(c[0]), "+f"(c[1]), "+f"(c[2]), "+f"(c[3])
        : "r"(a[0]), "r"(a[1]), "r"(a[2]), "r"(a[3]), "r"(b[0]), "r"(b[1]));
}

__device__ __forceinline__ void ldsm_x4(uint32_t* r, uint32_t addr) {
    asm volatile(
        "ldmatrix.sync.aligned.m8n8.x4.shared.b16 {%0,%1,%2,%3}, [%4];"
        : "=r"(r[0]), "=r"(r[1]), "=r"(r[2]), "=r"(r[3]) : "r"(addr));
}

__device__ __forceinline__ void cp_async16(uint32_t smem_addr, const void* gptr) {
    asm volatile("cp.async.cg.shared.global [%0], [%1], 16;\n"
                 :: "r"(smem_addr), "l"(gptr));
}
__device__ __forceinline__ void cp_commit() {
    asm volatile("cp.async.commit_group;\n");
}
__device__ __forceinline__ void sts_v2(uint32_t addr, float a, float b) {
    asm volatile("st.shared.v2.f32 [%0], {%1,%2};\n"
                 :: "r"(addr), "f"(a), "f"(b) : "memory");
}
__device__ __forceinline__ void lds_v4(uint32_t addr, float& a, float& b,
                                       float& c, float& d) {
    asm volatile("ld.shared.v4.f32 {%0,%1,%2,%3}, [%4];"
                 : "=f"(a), "=f"(b), "=f"(c), "=f"(d) : "r"(addr));
}
__device__ __forceinline__ void st_cs_f4(float* p, float a, float b,
                                         float c, float d) {
    asm volatile("st.global.cs.v4.f32 [%0], {%1,%2,%3,%4};"
                 :: "l"(p), "f"(a), "f"(b), "f"(c), "f"(d) : "memory");
}

__global__ __launch_bounds__(256, 2)
void gemm_f16_kernel(float* __restrict__ out, int N, int S) {
    extern __shared__ char sm[];
    const int tid  = threadIdx.x;
    const int lane = tid & 31;
    const int wid  = tid >> 5;
    const int wm   = wid & 1;        // 2 warp rows of 64
    const int wn   = wid >> 1;       // 4 warp cols of 32
    const int gid  = lane >> 2;      // 0..7
    const int tg   = lane & 3;       // 0..3

    const int m0 = blockIdx.x * TM;
    const int n0 = blockIdx.y * (TN * NJ);

    uint32_t sbase;
    asm("{ .reg .u64 t; cvta.to.shared.u64 t, %1; cvt.u32.u64 %0, t; }"
        : "=r"(sbase) : "l"(sm));
    const uint32_t Ab = sbase;
    const uint32_t Bb = sbase + A_BYTES;
    const uint32_t slab = sbase + A_BYTES + B_BYTES + (uint32_t)(wid * 4096);

    // ---- A prefetch (once per CTA) ----
#pragma unroll
    for (int i = 0; i < 8; i++) {
        int f = tid + i * 256;
        int r = f >> 4, q = f & 15;
        uint32_t dst = Ab + (uint32_t)(r * 256 + ((q ^ (r & 7)) << 4));
        cp_async16(dst, g_x + (size_t)(m0 + r) * DIM + q * 8);
    }
    cp_commit();

    auto prefetchB = [&](int nt0) {
#pragma unroll
        for (int i = 0; i < 8; i++) {
            int f = tid + i * 256;
            int r = f >> 4, q = f & 15;
            uint32_t dst = Bb + (uint32_t)(r * 256 + ((q ^ (r & 7)) << 4));
            cp_async16(dst, g_w + (size_t)(nt0 + r) * DIM + q * 8);
        }
        cp_commit();
    };
    prefetchB(n0);

    // ---- ldmatrix per-lane row assignments (proven rounds 8-13) ----
    const int rowA = (lane & 15);
    const int selA = (lane >> 4) & 1;
    const int rowB = (lane & 7) + ((lane & 16) >> 1);
    const int selB = (lane >> 3) & 1;
    const int swzA = rowA & 7;
    const int swzB = rowB & 7;

    uint32_t aAddr[4], bAddr[2];
#pragma unroll
    for (int mi = 0; mi < 4; mi++)
        aAddr[mi] = Ab + (uint32_t)((wm * 64 + mi * 16 + rowA) * 256);
#pragma unroll
    for (int nj = 0; nj < 2; nj++)
        bAddr[nj] = Bb + (uint32_t)((wn * 32 + nj * 16 + rowB) * 256);

    const int k8 = lane & 7;        // epilogue read lane mapping
    const int r4 = lane >> 3;

#pragma unroll
    for (int j = 0; j < NJ; j++) {
        asm volatile("cp.async.wait_group 0;\n");
        __syncthreads();

        float c[4][4][4];
#pragma unroll
        for (int mi = 0; mi < 4; mi++)
#pragma unroll
            for (int ni = 0; ni < 4; ni++)
#pragma unroll
                for (int jj = 0; jj < 4; jj++) c[mi][ni][jj] = 0.0f;

#pragma unroll
        for (int ks = 0; ks < 8; ks++) {
            const uint32_t offA = (uint32_t)(((2 * ks + selA) ^ swzA) << 4);
            const uint32_t offB = (uint32_t)(((2 * ks + selB) ^ swzB) << 4);
            uint32_t a[4][4], b[2][4];
#pragma unroll
            for (int mi = 0; mi < 4; mi++)
                ldsm_x4(a[mi], aAddr[mi] + offA);
#pragma unroll
            for (int nj = 0; nj < 2; nj++)
                ldsm_x4(b[nj], bAddr[nj] + offB);
#pragma unroll
            for (int mi = 0; mi < 4; mi++) {
#pragma unroll
                for (int ni = 0; ni < 4; ni++)
                    mma_f16(c[mi][ni], a[mi], &b[ni >> 1][(ni & 1) * 2]);
            }
        }
        __syncthreads();   // B reads done -> safe to refill

        const int nt0 = n0 + j * TN;
        if (j + 1 < NJ) prefetchB(nt0 + TN);   // hides under epilogue

        // ---- bias (hoisted per ni) ----
        float bb0[4], bb1[4];
#pragma unroll
        for (int ni = 0; ni < 4; ni++) {
            int col = nt0 + wn * 32 + ni * 8 + 2 * tg;
            bb0[ni] = g_bias[col];
            bb1[ni] = g_bias[col + 1];
        }

        // ---- staged epilogue: 2 passes of 32 rows, warp-private slab ----
#pragma unroll
        for (int pass = 0; pass < 2; pass++) {
#pragma unroll
            for (int mh = 0; mh < 2; mh++) {
                const int mi = pass * 2 + mh;
#pragma unroll
                for (int h = 0; h < 2; h++) {
                    const int lr = mh * 16 + h * 8 + gid;
#pragma unroll
                    for (int ni = 0; ni < 4; ni++) {
                        const int p = ((4 * ni + tg) + 4 * gid) & 15;
                        sts_v2(slab + (uint32_t)(lr * 128 + p * 8),
                               c[mi][ni][h * 2 + 0] + bb0[ni],
                               c[mi][ni][h * 2 + 1] + bb1[ni]);
                    }
                }
            }
            __syncwarp();
#pragma unroll
            for (int it = 0; it < 8; it++) {
                const int lr = it * 4 + r4;
                const int p0 = (2 * k8 + 4 * (lr & 7)) & 15;
                float v0, v1, v2, v3;
                lds_v4(slab + (uint32_t)(lr * 128 + p0 * 8), v0, v1, v2, v3);
                const int grow = m0 + wm * 64 + pass * 32 + lr;
                const int gcol = nt0 + wn * 32 + k8 * 4;
                st_cs_f4(out + (size_t)grow * S + gcol, v0, v1, v2, v3);
            }
            __syncwarp();
        }
    }
}

// ---------------------------------------------------------------------------
extern "C" void kernel_launch(void* const* d_in, const int* in_sizes, int n_in,
                              void* d_out, int out_size) {
    const float* x    = (const float*)d_in[0];
    const float* w    = (const float*)d_in[1];
    const float* bias = (const float*)d_in[2];
    const void*  ids  = d_in[3];

    const int N = in_sizes[0] / DIM;   // 4096
    const int S = in_sizes[3];         // 32768

    static int smem_set = 0;
    if (!smem_set) {
        cudaFuncSetAttribute(gemm_f16_kernel,
                             cudaFuncAttributeMaxDynamicSharedMemorySize,
                             SM_TOTAL);
        smem_set = 1;
    }

    long long base  = (long long)N * (long long)S;
    long long extra = (long long)out_size - base;

    init_flag_kernel<<<1, 1>>>();
    detect_ids_kernel<<<64, 256>>>(ids, S);
    prep_kernel<<<288, 256>>>(x, w, bias, ids, d_out, base, extra, N, S);

    dim3 grid(N / TM, S / (TN * NJ));
    gemm_f16_kernel<<<grid, 256, SM_TOTAL>>>((float*)d_out, N, S);
}